// round 1
// baseline (speedup 1.0000x reference)
#include <cuda_runtime.h>

// Problem constants (fixed by the dataset)
#define NB 2048   // batch
#define PP 196    // patches
#define DD 768    // patch dim
#define OO 512    // output dim
#define KT 16     // top-k

// Scratch (allocation-free rule: __device__ globals)
__device__ int   g_topk[NB * KT];
__device__ float g_local[NB * OO];

// ---------------------------------------------------------------------------
// Kernel 1: per-patch squared L2 norms + top-16 selection (set semantics; max
// over k later is order-invariant, squared norm is monotone in norm)
// ---------------------------------------------------------------------------
__global__ void norm_topk_kernel(const float* __restrict__ pt) {
    int n = blockIdx.x;
    __shared__ float norms[PP];
    __shared__ float rv[256];
    __shared__ int   ri[256];

    const float* base = pt + (size_t)n * PP * DD;
    int warp = threadIdx.x >> 5, lane = threadIdx.x & 31;

    for (int p = warp; p < PP; p += 8) {
        const float4* row = (const float4*)(base + p * DD);
        float s = 0.f;
        #pragma unroll
        for (int j = 0; j < (DD / 4) / 32; j++) {   // 6 iters
            float4 q = row[j * 32 + lane];
            s += q.x * q.x + q.y * q.y + q.z * q.z + q.w * q.w;
        }
        #pragma unroll
        for (int o = 16; o; o >>= 1) s += __shfl_xor_sync(0xffffffffu, s, o);
        if (lane == 0) norms[p] = s;
    }
    __syncthreads();

    int t = threadIdx.x;
    for (int it = 0; it < KT; it++) {
        rv[t] = (t < PP) ? norms[t] : -1.f;
        ri[t] = t;
        __syncthreads();
        #pragma unroll
        for (int s = 128; s > 0; s >>= 1) {
            if (t < s) {
                if (rv[t + s] > rv[t]) { rv[t] = rv[t + s]; ri[t] = ri[t + s]; }
            }
            __syncthreads();
        }
        if (t == 0) {
            g_topk[n * KT + it] = ri[0];
            norms[ri[0]] = -2.f;
        }
        __syncthreads();
    }
}

// ---------------------------------------------------------------------------
// Kernel 2: gathered GEMM  C[m,o] = sum_d A[m,d] * Wp[o,d]   (m = n*16 + slot)
// then max over the 16 slots per n  ->  g_local[n,o]
// Tiling: BM=64, BN=64, BK=32, 256 threads, 4x4 micro-tile.
// ---------------------------------------------------------------------------
__global__ void gemm_local_kernel(const float* __restrict__ pt,
                                  const float* __restrict__ Wp) {
    __shared__ float As[64][36];   // [m][k], pad 36 floats (144B, 16B-aligned)
    __shared__ float Bs[32][64];   // [k][o]
    __shared__ int   aoff[64];
    __shared__ float Cs[64][64];

    int tid = threadIdx.x;
    int bm = blockIdx.y, bn = blockIdx.x;

    if (tid < 64) {
        int m = bm * 64 + tid;
        int n = m >> 4, slot = m & 15;
        int p = g_topk[n * KT + slot];
        aoff[tid] = (n * PP + p) * DD;
    }
    __syncthreads();

    int tx = tid & 15, ty = tid >> 4;
    int lr = tid >> 2;              // load row (A) / load col (B)
    int lk = (tid & 3) * 8;         // k offset within tile

    float acc[4][4] = {};

    for (int kt = 0; kt < DD; kt += 32) {
        // --- load A tile: each thread 8 contiguous floats along k
        const float4* ap = (const float4*)(pt + aoff[lr] + kt + lk);
        float4 a0 = ap[0], a1 = ap[1];
        *(float4*)&As[lr][lk]     = a0;
        *(float4*)&As[lr][lk + 4] = a1;

        // --- load B tile (W_patch is [O, D] row-major; contiguous along k)
        const float4* bp = (const float4*)(Wp + (size_t)(bn * 64 + lr) * DD + kt + lk);
        float4 b0 = bp[0], b1 = bp[1];
        Bs[lk + 0][lr] = b0.x; Bs[lk + 1][lr] = b0.y;
        Bs[lk + 2][lr] = b0.z; Bs[lk + 3][lr] = b0.w;
        Bs[lk + 4][lr] = b1.x; Bs[lk + 5][lr] = b1.y;
        Bs[lk + 6][lr] = b1.z; Bs[lk + 7][lr] = b1.w;
        __syncthreads();

        #pragma unroll
        for (int kk = 0; kk < 32; kk++) {
            float ar0 = As[ty * 4 + 0][kk];
            float ar1 = As[ty * 4 + 1][kk];
            float ar2 = As[ty * 4 + 2][kk];
            float ar3 = As[ty * 4 + 3][kk];
            float4 b = *(float4*)&Bs[kk][tx * 4];
            acc[0][0] += ar0 * b.x; acc[0][1] += ar0 * b.y; acc[0][2] += ar0 * b.z; acc[0][3] += ar0 * b.w;
            acc[1][0] += ar1 * b.x; acc[1][1] += ar1 * b.y; acc[1][2] += ar1 * b.z; acc[1][3] += ar1 * b.w;
            acc[2][0] += ar2 * b.x; acc[2][1] += ar2 * b.y; acc[2][2] += ar2 * b.z; acc[2][3] += ar2 * b.w;
            acc[3][0] += ar3 * b.x; acc[3][1] += ar3 * b.y; acc[3][2] += ar3 * b.z; acc[3][3] += ar3 * b.w;
        }
        __syncthreads();
    }

    // stage C, then max-reduce over 16-row groups
    #pragma unroll
    for (int i = 0; i < 4; i++)
        #pragma unroll
        for (int j = 0; j < 4; j++)
            Cs[ty * 4 + i][tx * 4 + j] = acc[i][j];
    __syncthreads();

    int g = tid >> 6;        // 0..3 (n within block)
    int o = tid & 63;
    float m = Cs[g * 16][o];
    #pragma unroll
    for (int r = 1; r < 16; r++) m = fmaxf(m, Cs[g * 16 + r][o]);
    int n = bm * 4 + g;
    g_local[(size_t)n * OO + bn * 64 + o] = m;
}

// ---------------------------------------------------------------------------
// Kernel 3: fusion GEMM  out[n,o] = sum_c [cls|local][n,c] * Wf[o,c]
// M=2048, K=1024, N=512.  Same tiling as kernel 2.
// ---------------------------------------------------------------------------
__global__ void gemm_fuse_kernel(const float* __restrict__ cls,
                                 const float* __restrict__ Wf,
                                 float* __restrict__ out) {
    __shared__ float As[64][36];
    __shared__ float Bs[32][64];

    int tid = threadIdx.x;
    int bm = blockIdx.y, bn = blockIdx.x;
    int tx = tid & 15, ty = tid >> 4;
    int lr = tid >> 2;
    int lk = (tid & 3) * 8;

    float acc[4][4] = {};

    for (int kt = 0; kt < 2 * OO; kt += 32) {
        // A source: first 512 cols = cls_feat, next 512 = g_local (tile never straddles)
        const float* asrc = (kt < OO)
            ? (cls     + (size_t)(bm * 64 + lr) * OO + kt        + lk)
            : (g_local + (size_t)(bm * 64 + lr) * OO + (kt - OO) + lk);
        float4 a0 = ((const float4*)asrc)[0], a1 = ((const float4*)asrc)[1];
        *(float4*)&As[lr][lk]     = a0;
        *(float4*)&As[lr][lk + 4] = a1;

        const float4* bp = (const float4*)(Wf + (size_t)(bn * 64 + lr) * (2 * OO) + kt + lk);
        float4 b0 = bp[0], b1 = bp[1];
        Bs[lk + 0][lr] = b0.x; Bs[lk + 1][lr] = b0.y;
        Bs[lk + 2][lr] = b0.z; Bs[lk + 3][lr] = b0.w;
        Bs[lk + 4][lr] = b1.x; Bs[lk + 5][lr] = b1.y;
        Bs[lk + 6][lr] = b1.z; Bs[lk + 7][lr] = b1.w;
        __syncthreads();

        #pragma unroll
        for (int kk = 0; kk < 32; kk++) {
            float ar0 = As[ty * 4 + 0][kk];
            float ar1 = As[ty * 4 + 1][kk];
            float ar2 = As[ty * 4 + 2][kk];
            float ar3 = As[ty * 4 + 3][kk];
            float4 b = *(float4*)&Bs[kk][tx * 4];
            acc[0][0] += ar0 * b.x; acc[0][1] += ar0 * b.y; acc[0][2] += ar0 * b.z; acc[0][3] += ar0 * b.w;
            acc[1][0] += ar1 * b.x; acc[1][1] += ar1 * b.y; acc[1][2] += ar1 * b.z; acc[1][3] += ar1 * b.w;
            acc[2][0] += ar2 * b.x; acc[2][1] += ar2 * b.y; acc[2][2] += ar2 * b.z; acc[2][3] += ar2 * b.w;
            acc[3][0] += ar3 * b.x; acc[3][1] += ar3 * b.y; acc[3][2] += ar3 * b.z; acc[3][3] += ar3 * b.w;
        }
        __syncthreads();
    }

    #pragma unroll
    for (int i = 0; i < 4; i++) {
        int row = bm * 64 + ty * 4 + i;
        #pragma unroll
        for (int j = 0; j < 4; j++)
            out[(size_t)row * OO + bn * 64 + tx * 4 + j] = acc[i][j];
    }
}

// ---------------------------------------------------------------------------
// Kernel 4: row L2 normalize in-place (eps clamp matches reference)
// ---------------------------------------------------------------------------
__global__ void normalize_kernel(float* __restrict__ out) {
    int n = blockIdx.x;
    float* row = out + (size_t)n * OO;
    __shared__ float red[8];

    int t = threadIdx.x;                       // 256 threads, 512 floats
    float2 v = ((float2*)row)[t];
    float s = v.x * v.x + v.y * v.y;
    #pragma unroll
    for (int o = 16; o; o >>= 1) s += __shfl_xor_sync(0xffffffffu, s, o);
    if ((t & 31) == 0) red[t >> 5] = s;
    __syncthreads();
    if (t == 0) {
        float tot = 0.f;
        #pragma unroll
        for (int w = 0; w < 8; w++) tot += red[w];
        red[0] = tot;
    }
    __syncthreads();
    float nrm = sqrtf(red[0]);
    float inv = 1.f / fmaxf(nrm, 1e-12f);
    v.x *= inv; v.y *= inv;
    ((float2*)row)[t] = v;
}

// ---------------------------------------------------------------------------
extern "C" void kernel_launch(void* const* d_in, const int* in_sizes, int n_in,
                              void* d_out, int out_size) {
    const float* cls = (const float*)d_in[0];   // (2048, 512)
    const float* pt  = (const float*)d_in[1];   // (2048, 196, 768)
    const float* Wp  = (const float*)d_in[2];   // (512, 768)
    const float* Wf  = (const float*)d_in[3];   // (512, 1024)
    float* out = (float*)d_out;                 // (2048, 512)

    norm_topk_kernel<<<NB, 256>>>(pt);
    gemm_local_kernel<<<dim3(OO / 64, NB * KT / 64), 256>>>(pt, Wp);
    gemm_fuse_kernel<<<dim3(OO / 64, NB / 64), 256>>>(cls, Wf, out);
    normalize_kernel<<<NB, 256>>>(out);
}